// round 13
// baseline (speedup 1.0000x reference)
#include <cuda_runtime.h>
#include <cstdint>

#define NTH 128               // 4 warps
#define RPW 32                // output rows per warp
#define STAGES 4              // cp.async ring; 2 stages consumed per iteration

__device__ __forceinline__ void cp_async16(uint32_t saddr, const void* gptr) {
    asm volatile("cp.async.cg.shared.global [%0], [%1], 16;\n"
                 :: "r"(saddr), "l"(gptr) : "memory");
}
__device__ __forceinline__ void cp_commit() {
    asm volatile("cp.async.commit_group;\n" ::: "memory");
}
template <int N>
__device__ __forceinline__ void cp_wait() {
    asm volatile("cp.async.wait_group %0;\n" :: "n"(N) : "memory");
}

__global__ __launch_bounds__(NTH)
void conv3x3_v13(const float* __restrict__ X,
                 const float* __restrict__ Kp,
                 float* __restrict__ O,
                 int H, int W)
{
    // warp-private ring: [warp][stage][256 floats] (1KB per row)
    __shared__ float buf[4][STAGES][256];

    const int bc = blockIdx.z;
    const float* __restrict__ Xp = X + (size_t)bc * H * W;
    float* __restrict__ Op       = O + (size_t)bc * H * W;

    const float k00 = __ldg(&Kp[0]), k01 = __ldg(&Kp[1]), k02 = __ldg(&Kp[2]);
    const float k10 = __ldg(&Kp[3]), k11 = __ldg(&Kp[4]), k12 = __ldg(&Kp[5]);
    const float k20 = __ldg(&Kp[6]), k21 = __ldg(&Kp[7]), k22 = __ldg(&Kp[8]);

    const int tid  = threadIdx.x;
    const int warp = tid >> 5;
    const int lane = tid & 31;
    const int y0   = blockIdx.y * (4 * RPW) + warp * RPW;

    const int W4g = W >> 2;   // 64
    float4* __restrict__ Op4 = (float4*)Op;
    const float4 Z = make_float4(0.f, 0.f, 0.f, 0.f);

    float* wbase = &buf[warp][0][0];
    const uint32_t sbase = (uint32_t)__cvta_generic_to_shared(wbase) + lane * 16u;

    // issue row t into stage s; always commits exactly one group
    auto issue_row = [&](int t, int s, bool valid) {
        if (valid && t >= 0 && t < H) {
            const float* g = Xp + (size_t)t * W + lane * 4;
            const uint32_t a = sbase + (uint32_t)s * 1024u;
            cp_async16(a,        g);
            cp_async16(a + 512u, g + 128);
        } else if (valid) {
            float4* d = (float4*)(wbase + s * 256 + lane * 4);
            d[0]  = Z;
            d[32] = Z;
        }
        cp_commit();
    };

    // prologue: rows y0-1 .. y0+2 into stages 0..3
    #pragma unroll
    for (int s = 0; s < STAGES; s++)
        issue_row(y0 - 1 + s, s, true);

    float4 pLo = Z, pHi = Z;   // out row t-1 (awaiting kernel row 2)
    float4 qLo = Z, qHi = Z;   // out row t   (awaiting rows 1,2)
    float4 rLo, rHi;           // out row t+1 (kernel row 0 partial)

    // pair loop: i = 0,2,...,32 -> input rows (t, t+1) = (y0-1+i, y0+i)
    #pragma unroll 1
    for (int i = 0; i <= RPW; i += 2) {
        const int t = y0 - 1 + i;
        const int s = i & 3;          // stages {0,1} or {2,3}

        cp_wait<STAGES - 2>();        // both consumed stages complete

        const float4* src0 = (const float4*)(wbase + s * 256 + lane * 4);
        const float4* src1 = (const float4*)(wbase + (s + 1) * 256 + lane * 4);
        const float4 vLo = src0[0];
        const float4 vHi = src0[32];
        const float4 wLo = src1[0];
        const float4 wHi = src1[32];

        // refill both stages back-to-back (batched load issue)
        const bool rv = (i + STAGES) <= RPW;
        issue_row(t + STAGES,     s,     rv);
        issue_row(t + STAGES + 1, s + 1, rv);

        const bool st = (i >= 2);

        // ---------- row t (v) ----------
        {
            const float up0 = __shfl_up_sync(0xffffffffu,   vLo.w, 1);
            const float dn0 = __shfl_down_sync(0xffffffffu, vLo.x, 1);
            const float up1 = __shfl_up_sync(0xffffffffu,   vHi.w, 1);
            const float dn1 = __shfl_down_sync(0xffffffffu, vHi.x, 1);
            const float cL  = __shfl_sync(0xffffffffu, vLo.w, 31);
            const float cR  = __shfl_sync(0xffffffffu, vHi.x, 0);
            const float Ll = (lane == 0)  ? 0.f : up0;
            const float Rl = (lane == 31) ? cR  : dn0;
            const float Lh = (lane == 0)  ? cL  : up1;
            const float Rh = (lane == 31) ? 0.f : dn1;

            // out row t-1 completes (kernel row 2)
            pLo.x += k20 * Ll    + k21 * vLo.x + k22 * vLo.y;
            pLo.y += k20 * vLo.x + k21 * vLo.y + k22 * vLo.z;
            pLo.z += k20 * vLo.y + k21 * vLo.z + k22 * vLo.w;
            pLo.w += k20 * vLo.z + k21 * vLo.w + k22 * Rl;
            pHi.x += k20 * Lh    + k21 * vHi.x + k22 * vHi.y;
            pHi.y += k20 * vHi.x + k21 * vHi.y + k22 * vHi.z;
            pHi.z += k20 * vHi.y + k21 * vHi.z + k22 * vHi.w;
            pHi.w += k20 * vHi.z + k21 * vHi.w + k22 * Rh;
            if (st) {
                const size_t rb = (size_t)(t - 1) * W4g;
                Op4[rb + lane]      = pLo;
                Op4[rb + lane + 32] = pHi;
            }

            // out row t: += kernel row 1
            qLo.x += k10 * Ll    + k11 * vLo.x + k12 * vLo.y;
            qLo.y += k10 * vLo.x + k11 * vLo.y + k12 * vLo.z;
            qLo.z += k10 * vLo.y + k11 * vLo.z + k12 * vLo.w;
            qLo.w += k10 * vLo.z + k11 * vLo.w + k12 * Rl;
            qHi.x += k10 * Lh    + k11 * vHi.x + k12 * vHi.y;
            qHi.y += k10 * vHi.x + k11 * vHi.y + k12 * vHi.z;
            qHi.z += k10 * vHi.y + k11 * vHi.z + k12 * vHi.w;
            qHi.w += k10 * vHi.z + k11 * vHi.w + k12 * Rh;

            // out row t+1: kernel row 0
            rLo.x = k00 * Ll    + k01 * vLo.x + k02 * vLo.y;
            rLo.y = k00 * vLo.x + k01 * vLo.y + k02 * vLo.z;
            rLo.z = k00 * vLo.y + k01 * vLo.z + k02 * vLo.w;
            rLo.w = k00 * vLo.z + k01 * vLo.w + k02 * Rl;
            rHi.x = k00 * Lh    + k01 * vHi.x + k02 * vHi.y;
            rHi.y = k00 * vHi.x + k01 * vHi.y + k02 * vHi.z;
            rHi.z = k00 * vHi.y + k01 * vHi.z + k02 * vHi.w;
            rHi.w = k00 * vHi.z + k01 * vHi.w + k02 * Rh;
        }

        // ---------- row t+1 (w) ----------
        {
            const float up0 = __shfl_up_sync(0xffffffffu,   wLo.w, 1);
            const float dn0 = __shfl_down_sync(0xffffffffu, wLo.x, 1);
            const float up1 = __shfl_up_sync(0xffffffffu,   wHi.w, 1);
            const float dn1 = __shfl_down_sync(0xffffffffu, wHi.x, 1);
            const float cL  = __shfl_sync(0xffffffffu, wLo.w, 31);
            const float cR  = __shfl_sync(0xffffffffu, wHi.x, 0);
            const float Ll = (lane == 0)  ? 0.f : up0;
            const float Rl = (lane == 31) ? cR  : dn0;
            const float Lh = (lane == 0)  ? cL  : up1;
            const float Rh = (lane == 31) ? 0.f : dn1;

            // out row t completes (kernel row 2)
            qLo.x += k20 * Ll    + k21 * wLo.x + k22 * wLo.y;
            qLo.y += k20 * wLo.x + k21 * wLo.y + k22 * wLo.z;
            qLo.z += k20 * wLo.y + k21 * wLo.z + k22 * wLo.w;
            qLo.w += k20 * wLo.z + k21 * wLo.w + k22 * Rl;
            qHi.x += k20 * Lh    + k21 * wHi.x + k22 * wHi.y;
            qHi.y += k20 * wHi.x + k21 * wHi.y + k22 * wHi.z;
            qHi.z += k20 * wHi.y + k21 * wHi.z + k22 * wHi.w;
            qHi.w += k20 * wHi.z + k21 * wHi.w + k22 * Rh;
            if (st) {
                const size_t rb = (size_t)t * W4g;
                Op4[rb + lane]      = qLo;
                Op4[rb + lane + 32] = qHi;
            }

            // out row t+1: += kernel row 1 (accumulate into r)
            rLo.x += k10 * Ll    + k11 * wLo.x + k12 * wLo.y;
            rLo.y += k10 * wLo.x + k11 * wLo.y + k12 * wLo.z;
            rLo.z += k10 * wLo.y + k11 * wLo.z + k12 * wLo.w;
            rLo.w += k10 * wLo.z + k11 * wLo.w + k12 * Rl;
            rHi.x += k10 * Lh    + k11 * wHi.x + k12 * wHi.y;
            rHi.y += k10 * wHi.x + k11 * wHi.y + k12 * wHi.z;
            rHi.z += k10 * wHi.y + k11 * wHi.z + k12 * wHi.w;
            rHi.w += k10 * wHi.z + k11 * wHi.w + k12 * Rh;

            // roll: p <- r (out t+1 partial), q <- kernel row 0 of w (out t+2)
            pLo = rLo; pHi = rHi;
            qLo.x = k00 * Ll    + k01 * wLo.x + k02 * wLo.y;
            qLo.y = k00 * wLo.x + k01 * wLo.y + k02 * wLo.z;
            qLo.z = k00 * wLo.y + k01 * wLo.z + k02 * wLo.w;
            qLo.w = k00 * wLo.z + k01 * wLo.w + k02 * Rl;
            qHi.x = k00 * Lh    + k01 * wHi.x + k02 * wHi.y;
            qHi.y = k00 * wHi.x + k01 * wHi.y + k02 * wHi.z;
            qHi.z = k00 * wHi.y + k01 * wHi.z + k02 * wHi.w;
            qHi.w = k00 * wHi.z + k01 * wHi.w + k02 * Rh;
        }
    }
}

extern "C" void kernel_launch(void* const* d_in, const int* in_sizes, int n_in,
                              void* d_out, int out_size)
{
    const float* X = (const float*)d_in[0];   // (16, 64, 256, 256) fp32
    const float* K = (const float*)d_in[1];   // (3, 3) fp32
    float* O = (float*)d_out;

    const int H = 256, W = 256;
    const int planes = in_sizes[0] / (H * W); // 1024

    dim3 block(NTH, 1, 1);
    dim3 grid(1, H / (4 * RPW), planes);      // (1, 2, 1024) = 2048 blocks
    conv3x3_v13<<<grid, block>>>(X, K, O, H, W);
}

// round 14
// speedup vs baseline: 1.0039x; 1.0039x over previous
#include <cuda_runtime.h>
#include <cstdint>

#define NTH 64                // 2 warps per block (finer scheduling granularity)
#define NWARPS (NTH / 32)
#define RPW 32                // output rows per warp
#define STAGES 4              // cp.async ring depth (rows in flight per warp)

__device__ __forceinline__ void cp_async16(uint32_t saddr, const void* gptr) {
    asm volatile("cp.async.cg.shared.global [%0], [%1], 16;\n"
                 :: "r"(saddr), "l"(gptr) : "memory");
}
__device__ __forceinline__ void cp_commit() {
    asm volatile("cp.async.commit_group;\n" ::: "memory");
}
template <int N>
__device__ __forceinline__ void cp_wait() {
    asm volatile("cp.async.wait_group %0;\n" :: "n"(N) : "memory");
}

__global__ __launch_bounds__(NTH)
void conv3x3_v14(const float* __restrict__ X,
                 const float* __restrict__ Kp,
                 float* __restrict__ O,
                 int H, int W)
{
    // warp-private ring: [warp][stage][256 floats] (1KB per row)
    __shared__ float buf[NWARPS][STAGES][256];

    const int bc = blockIdx.z;
    const float* __restrict__ Xp = X + (size_t)bc * H * W;
    float* __restrict__ Op       = O + (size_t)bc * H * W;

    const float k00 = __ldg(&Kp[0]), k01 = __ldg(&Kp[1]), k02 = __ldg(&Kp[2]);
    const float k10 = __ldg(&Kp[3]), k11 = __ldg(&Kp[4]), k12 = __ldg(&Kp[5]);
    const float k20 = __ldg(&Kp[6]), k21 = __ldg(&Kp[7]), k22 = __ldg(&Kp[8]);

    const int tid  = threadIdx.x;
    const int warp = tid >> 5;
    const int lane = tid & 31;
    const int y0   = blockIdx.y * (NWARPS * RPW) + warp * RPW;

    const int W4g = W >> 2;   // 64
    float4* __restrict__ Op4 = (float4*)Op;
    const float4 Z = make_float4(0.f, 0.f, 0.f, 0.f);

    float* wbase = &buf[warp][0][0];
    const uint32_t sbase = (uint32_t)__cvta_generic_to_shared(wbase) + lane * 16u;

    // issue row t into stage s; always commits exactly one group
    auto issue_row = [&](int t, int s, bool valid) {
        if (valid && t >= 0 && t < H) {
            const float* g = Xp + (size_t)t * W + lane * 4;
            const uint32_t a = sbase + (uint32_t)s * 1024u;
            cp_async16(a,        g);
            cp_async16(a + 512u, g + 128);
        } else if (valid) {
            float4* d = (float4*)(wbase + s * 256 + lane * 4);
            d[0]  = Z;
            d[32] = Z;
        }
        cp_commit();
    };

    // prologue: rows y0-1 .. y0+2 into stages 0..3
    #pragma unroll
    for (int s = 0; s < STAGES; s++)
        issue_row(y0 - 1 + s, s, true);

    float4 pLo = Z, pHi = Z;   // out row t-1 (awaiting kernel row 2)
    float4 qLo = Z, qHi = Z;   // out row t+1 partial (kernel row 0)

    #pragma unroll 2
    for (int i = 0; i <= RPW + 1; i++) {
        const int t = y0 - 1 + i;
        const int s = i & (STAGES - 1);

        cp_wait<STAGES - 1>();   // oldest group (stage s) complete

        // read this lane's own bytes back (no cross-thread smem reads -> no sync)
        const float4* src = (const float4*)(wbase + s * 256 + lane * 4);
        const float4 vLo = src[0];
        const float4 vHi = src[32];

        // refill stage s with row t+STAGES (only if it will be consumed)
        issue_row(t + STAGES, s, (i + STAGES) <= RPW + 1);

        // horizontal neighbors: unconditional shuffles + value selects
        const float upLo = __shfl_up_sync(0xffffffffu,   vLo.w, 1);
        const float dnLo = __shfl_down_sync(0xffffffffu, vLo.x, 1);
        const float upHi = __shfl_up_sync(0xffffffffu,   vHi.w, 1);
        const float dnHi = __shfl_down_sync(0xffffffffu, vHi.x, 1);
        const float crossL = __shfl_sync(0xffffffffu, vLo.w, 31);
        const float crossR = __shfl_sync(0xffffffffu, vHi.x, 0);

        const float Llo = (lane == 0)  ? 0.f    : upLo;
        const float Rlo = (lane == 31) ? crossR : dnLo;
        const float Lhi = (lane == 0)  ? crossL : upHi;
        const float Rhi = (lane == 31) ? 0.f    : dnHi;

        // out row t-1 completes with kernel row 2 of input row t
        pLo.x += k20 * Llo   + k21 * vLo.x + k22 * vLo.y;
        pLo.y += k20 * vLo.x + k21 * vLo.y + k22 * vLo.z;
        pLo.z += k20 * vLo.y + k21 * vLo.z + k22 * vLo.w;
        pLo.w += k20 * vLo.z + k21 * vLo.w + k22 * Rlo;
        pHi.x += k20 * Lhi   + k21 * vHi.x + k22 * vHi.y;
        pHi.y += k20 * vHi.x + k21 * vHi.y + k22 * vHi.z;
        pHi.z += k20 * vHi.y + k21 * vHi.z + k22 * vHi.w;
        pHi.w += k20 * vHi.z + k21 * vHi.w + k22 * Rhi;
        if (i >= 2) {
            const size_t rb = (size_t)(t - 1) * W4g;
            Op4[rb + lane]      = pLo;
            Op4[rb + lane + 32] = pHi;
        }

        // out row t: previous partial + kernel row 1
        pLo.x = qLo.x + (k10 * Llo   + k11 * vLo.x + k12 * vLo.y);
        pLo.y = qLo.y + (k10 * vLo.x + k11 * vLo.y + k12 * vLo.z);
        pLo.z = qLo.z + (k10 * vLo.y + k11 * vLo.z + k12 * vLo.w);
        pLo.w = qLo.w + (k10 * vLo.z + k11 * vLo.w + k12 * Rlo);
        pHi.x = qHi.x + (k10 * Lhi   + k11 * vHi.x + k12 * vHi.y);
        pHi.y = qHi.y + (k10 * vHi.x + k11 * vHi.y + k12 * vHi.z);
        pHi.z = qHi.z + (k10 * vHi.y + k11 * vHi.z + k12 * vHi.w);
        pHi.w = qHi.w + (k10 * vHi.z + k11 * vHi.w + k12 * Rhi);

        // out row t+1: kernel row 0
        qLo.x = k00 * Llo   + k01 * vLo.x + k02 * vLo.y;
        qLo.y = k00 * vLo.x + k01 * vLo.y + k02 * vLo.z;
        qLo.z = k00 * vLo.y + k01 * vLo.z + k02 * vLo.w;
        qLo.w = k00 * vLo.z + k01 * vLo.w + k02 * Rlo;
        qHi.x = k00 * Lhi   + k01 * vHi.x + k02 * vHi.y;
        qHi.y = k00 * vHi.x + k01 * vHi.y + k02 * vHi.z;
        qHi.z = k00 * vHi.y + k01 * vHi.z + k02 * vHi.w;
        qHi.w = k00 * vHi.z + k01 * vHi.w + k02 * Rhi;
    }
}

extern "C" void kernel_launch(void* const* d_in, const int* in_sizes, int n_in,
                              void* d_out, int out_size)
{
    const float* X = (const float*)d_in[0];   // (16, 64, 256, 256) fp32
    const float* K = (const float*)d_in[1];   // (3, 3) fp32
    float* O = (float*)d_out;

    const int H = 256, W = 256;
    const int planes = in_sizes[0] / (H * W); // 1024

    dim3 block(NTH, 1, 1);
    dim3 grid(1, H / (NWARPS * RPW), planes); // (1, 4, 1024) = 4096 blocks
    conv3x3_v14<<<grid, block>>>(X, K, O, H, W);
}

// round 15
// speedup vs baseline: 1.0159x; 1.0119x over previous
#include <cuda_runtime.h>
#include <cstdint>

#define NTH 128               // 4 warps
#define RPW 32                // output rows per warp
#define STAGES 4              // cp.async ring depth (rows in flight per warp)

__device__ __forceinline__ void cp_async16(uint32_t saddr, const void* gptr) {
    asm volatile("cp.async.cg.shared.global [%0], [%1], 16;\n"
                 :: "r"(saddr), "l"(gptr) : "memory");
}
__device__ __forceinline__ void cp_commit() {
    asm volatile("cp.async.commit_group;\n" ::: "memory");
}
template <int N>
__device__ __forceinline__ void cp_wait() {
    asm volatile("cp.async.wait_group %0;\n" :: "n"(N) : "memory");
}

__global__ __launch_bounds__(NTH)
void conv3x3_v15(const float* __restrict__ X,
                 const float* __restrict__ Kp,
                 float* __restrict__ O,
                 int H, int W)
{
    // warp-private ring: [warp][stage][256 floats] (1KB per row)
    __shared__ float buf[4][STAGES][256];

    const int bc = blockIdx.z;
    const float* __restrict__ Xp = X + (size_t)bc * H * W;
    float* __restrict__ Op       = O + (size_t)bc * H * W;

    const float k00 = __ldg(&Kp[0]), k01 = __ldg(&Kp[1]), k02 = __ldg(&Kp[2]);
    const float k10 = __ldg(&Kp[3]), k11 = __ldg(&Kp[4]), k12 = __ldg(&Kp[5]);
    const float k20 = __ldg(&Kp[6]), k21 = __ldg(&Kp[7]), k22 = __ldg(&Kp[8]);

    const int tid  = threadIdx.x;
    const int warp = tid >> 5;
    const int lane = tid & 31;
    const int y0   = blockIdx.y * (4 * RPW) + warp * RPW;

    const int W4g = W >> 2;   // 64
    float4* __restrict__ Op4 = (float4*)Op;
    const float4 Z = make_float4(0.f, 0.f, 0.f, 0.f);

    float* wbase = &buf[warp][0][0];
    const uint32_t sbase = (uint32_t)__cvta_generic_to_shared(wbase) + lane * 16u;

    // issue row t into stage s; always commits exactly one group
    auto issue_row = [&](int t, int s, bool valid) {
        if (valid && t >= 0 && t < H) {
            const float* g = Xp + (size_t)t * W + lane * 4;
            const uint32_t a = sbase + (uint32_t)s * 1024u;
            cp_async16(a,        g);
            cp_async16(a + 512u, g + 128);
        } else if (valid) {
            float4* d = (float4*)(wbase + s * 256 + lane * 4);
            d[0]  = Z;
            d[32] = Z;
        }
        cp_commit();
    };

    // prologue: rows y0-1 .. y0+2 into stages 0..3
    #pragma unroll
    for (int s = 0; s < STAGES; s++)
        issue_row(y0 - 1 + s, s, true);

    float4 pLo = Z, pHi = Z;   // out row t-1 (awaiting kernel row 2)
    float4 qLo = Z, qHi = Z;   // out row t+1 partial (kernel row 0)

    // unroll 4: with STAGES=4, stage index (i & 3) becomes a compile-time
    // constant in each unrolled body -> all ring addressing folds to immediates
    #pragma unroll 4
    for (int i = 0; i <= RPW + 1; i++) {
        const int t = y0 - 1 + i;
        const int s = i & (STAGES - 1);

        cp_wait<STAGES - 1>();   // oldest group (stage s) complete

        // read this lane's own bytes back (no cross-thread smem reads -> no sync)
        const float4* src = (const float4*)(wbase + s * 256 + lane * 4);
        const float4 vLo = src[0];
        const float4 vHi = src[32];

        // refill stage s with row t+STAGES (only if it will be consumed)
        issue_row(t + STAGES, s, (i + STAGES) <= RPW + 1);

        // horizontal neighbors: unconditional shuffles + value selects
        const float upLo = __shfl_up_sync(0xffffffffu,   vLo.w, 1);
        const float dnLo = __shfl_down_sync(0xffffffffu, vLo.x, 1);
        const float upHi = __shfl_up_sync(0xffffffffu,   vHi.w, 1);
        const float dnHi = __shfl_down_sync(0xffffffffu, vHi.x, 1);
        const float crossL = __shfl_sync(0xffffffffu, vLo.w, 31);
        const float crossR = __shfl_sync(0xffffffffu, vHi.x, 0);

        const float Llo = (lane == 0)  ? 0.f    : upLo;
        const float Rlo = (lane == 31) ? crossR : dnLo;
        const float Lhi = (lane == 0)  ? crossL : upHi;
        const float Rhi = (lane == 31) ? 0.f    : dnHi;

        // out row t-1 completes with kernel row 2 of input row t
        pLo.x += k20 * Llo   + k21 * vLo.x + k22 * vLo.y;
        pLo.y += k20 * vLo.x + k21 * vLo.y + k22 * vLo.z;
        pLo.z += k20 * vLo.y + k21 * vLo.z + k22 * vLo.w;
        pLo.w += k20 * vLo.z + k21 * vLo.w + k22 * Rlo;
        pHi.x += k20 * Lhi   + k21 * vHi.x + k22 * vHi.y;
        pHi.y += k20 * vHi.x + k21 * vHi.y + k22 * vHi.z;
        pHi.z += k20 * vHi.y + k21 * vHi.z + k22 * vHi.w;
        pHi.w += k20 * vHi.z + k21 * vHi.w + k22 * Rhi;
        if (i >= 2) {
            const size_t rb = (size_t)(t - 1) * W4g;
            Op4[rb + lane]      = pLo;
            Op4[rb + lane + 32] = pHi;
        }

        // out row t: previous partial + kernel row 1
        pLo.x = qLo.x + (k10 * Llo   + k11 * vLo.x + k12 * vLo.y);
        pLo.y = qLo.y + (k10 * vLo.x + k11 * vLo.y + k12 * vLo.z);
        pLo.z = qLo.z + (k10 * vLo.y + k11 * vLo.z + k12 * vLo.w);
        pLo.w = qLo.w + (k10 * vLo.z + k11 * vLo.w + k12 * Rlo);
        pHi.x = qHi.x + (k10 * Lhi   + k11 * vHi.x + k12 * vHi.y);
        pHi.y = qHi.y + (k10 * vHi.x + k11 * vHi.y + k12 * vHi.z);
        pHi.z = qHi.z + (k10 * vHi.y + k11 * vHi.z + k12 * vHi.w);
        pHi.w = qHi.w + (k10 * vHi.z + k11 * vHi.w + k12 * Rhi);

        // out row t+1: kernel row 0
        qLo.x = k00 * Llo   + k01 * vLo.x + k02 * vLo.y;
        qLo.y = k00 * vLo.x + k01 * vLo.y + k02 * vLo.z;
        qLo.z = k00 * vLo.y + k01 * vLo.z + k02 * vLo.w;
        qLo.w = k00 * vLo.z + k01 * vLo.w + k02 * Rlo;
        qHi.x = k00 * Lhi   + k01 * vHi.x + k02 * vHi.y;
        qHi.y = k00 * vHi.x + k01 * vHi.y + k02 * vHi.z;
        qHi.z = k00 * vHi.y + k01 * vHi.z + k02 * vHi.w;
        qHi.w = k00 * vHi.z + k01 * vHi.w + k02 * Rhi;
    }
}

extern "C" void kernel_launch(void* const* d_in, const int* in_sizes, int n_in,
                              void* d_out, int out_size)
{
    const float* X = (const float*)d_in[0];   // (16, 64, 256, 256) fp32
    const float* K = (const float*)d_in[1];   // (3, 3) fp32
    float* O = (float*)d_out;

    const int H = 256, W = 256;
    const int planes = in_sizes[0] / (H * W); // 1024

    dim3 block(NTH, 1, 1);
    dim3 grid(1, H / (4 * RPW), planes);      // (1, 2, 1024) = 2048 blocks
    conv3x3_v15<<<grid, block>>>(X, K, O, H, W);
}